// round 4
// baseline (speedup 1.0000x reference)
#include <cuda_runtime.h>
#include <math_constants.h>

// Flash-attention style fused kernel:
//   out = softmax(p1 @ p2^T * sqrt(N2)) @ p2
// N1 = N2 = 8192, D = 128, all fp32.
//
// Round 2: packed f32x2 FMA (fma.rn.f32x2) in both GEMMs + bank-conflict-aware
// lane->data remapping so the smem crossbar (128 B/cyc/SM) stays below the
// doubled math rate. Scores remain exact fp32 (softmax near-argmax, scale
// sqrt(8192) makes low-precision scores fail rel_err 1e-3).

#define N1v 8192
#define N2v 8192
#define DD  128
#define BM  64
#define BN  64
#define KVPAD 132   // row stride (floats); 132*4 % 32 banks => lane-row stride 4mc: 2-way min
#define PPAD  68    // row stride for P tile (16B aligned rows)
#define NTHREADS 256

// sqrt(8192) * log2(e) : logits computed directly in log2 domain
#define C2F 130.57784f

// packed f32x2 ops (ptxas never auto-fuses these from C++)
#define FMA2(d, a, b) asm("fma.rn.f32x2 %0, %1, %2, %0;" : "+l"(d) : "l"(a), "l"(b))
#define MUL2(d, s)    asm("mul.rn.f32x2 %0, %0, %1;"     : "+l"(d) : "l"(s))
#define PACK2(d, x, y) asm("mov.b64 %0, {%1, %2};" : "=l"(d) : "f"(x), "f"(y))
#define UNPACK2(lo, hi, v) asm("mov.b64 {%0, %1}, %2;" : "=f"(lo), "=f"(hi) : "l"(v))

__global__ __launch_bounds__(NTHREADS, 1)
void attn_fwd_kernel(const float* __restrict__ P1,
                     const float* __restrict__ P2,
                     float* __restrict__ OUT)
{
    extern __shared__ float smem[];
    float* sq  = smem;                      // [BM][KVPAD]
    float* skv = sq  + BM * KVPAD;          // [BN][KVPAD]
    float* sp  = skv + BN * KVPAD;          // [BM][PPAD]

    const int t   = threadIdx.x;
    const int mr  = t >> 4;                 // 0..15  row-group id
    const int mc  = t & 15;                 // 0..15  lane within row-group
    const int r0  = mr * 4;                 // this thread's 4 score/output rows
    // GEMM1: this thread owns score columns {mc + 16*jj}, jj=0..3
    // GEMM2: this thread owns output cols {4mc..4mc+3} and {64+4mc..64+4mc+3}
    const int dcA = 4 * mc;
    const int dcB = 64 + 4 * mc;
    const int qbase = blockIdx.x * BM;

    // ---- load Q tile (BM x 128 floats = 2048 float4, 8 per thread) ----
    {
        const float4* src = (const float4*)(P1 + (size_t)qbase * DD);
        #pragma unroll
        for (int i = 0; i < 8; i++) {
            int idx = t + i * NTHREADS;       // 0..2047
            int row = idx >> 5;               // 32 float4 per row
            int c4  = idx & 31;
            float4 v = src[idx];
            *(float4*)&sq[row * KVPAD + c4 * 4] = v;
        }
    }

    // ---- running softmax state + packed O accumulators ----
    float m_run[4], l_run[4];
    unsigned long long o2[4][4];            // 4 rows x 4 col-pairs (8 cols)
    #pragma unroll
    for (int i = 0; i < 4; i++) {
        m_run[i] = -CUDART_INF_F;
        l_run[i] = 0.f;
        #pragma unroll
        for (int d = 0; d < 4; d++) o2[i][d] = 0ull;
    }

    __syncthreads();

    for (int jb = 0; jb < N2v; jb += BN) {
        // ---- load KV tile ----
        {
            const float4* src = (const float4*)(P2 + (size_t)jb * DD);
            #pragma unroll
            for (int i = 0; i < 8; i++) {
                int idx = t + i * NTHREADS;
                int row = idx >> 5;
                int c4  = idx & 31;
                float4 v = src[idx];
                *(float4*)&skv[row * KVPAD + c4 * 4] = v;
            }
        }
        __syncthreads();

        // ---- GEMM1 (packed k-pairs): acc2[i][jj] lanes hold (even-k, odd-k)
        //      partial sums of q[r0+i] . kv[mc+16*jj] ----
        unsigned long long acc2[4][4];
        #pragma unroll
        for (int i = 0; i < 4; i++)
            #pragma unroll
            for (int j = 0; j < 4; j++) acc2[i][j] = 0ull;

        #pragma unroll 2
        for (int k = 0; k < DD; k += 4) {
            ulonglong2 A[4], B[4];
            #pragma unroll
            for (int i = 0; i < 4; i++)       // broadcast within the 16-lane group
                A[i] = *(const ulonglong2*)&sq[(r0 + i) * KVPAD + k];
            #pragma unroll
            for (int j = 0; j < 4; j++)       // lane-varying rows: 2-way min conflicts
                B[j] = *(const ulonglong2*)&skv[(mc + 16 * j) * KVPAD + k];
            #pragma unroll
            for (int i = 0; i < 4; i++) {
                #pragma unroll
                for (int j = 0; j < 4; j++) {
                    FMA2(acc2[i][j], A[i].x, B[j].x);
                    FMA2(acc2[i][j], A[i].y, B[j].y);
                }
            }
        }

        // ---- online softmax (per row, reduced across the 16-lane row group) ----
        #pragma unroll
        for (int i = 0; i < 4; i++) {
            float s[4];
            #pragma unroll
            for (int j = 0; j < 4; j++) {
                float lo, hi;
                UNPACK2(lo, hi, acc2[i][j]);
                s[j] = lo + hi;
            }
            float mloc = fmaxf(fmaxf(s[0], s[1]), fmaxf(s[2], s[3]));
            mloc *= C2F;   // logits in log2 domain: s * sqrt(N2) * log2(e)
            #pragma unroll
            for (int off = 1; off < 16; off <<= 1)
                mloc = fmaxf(mloc, __shfl_xor_sync(0xffffffffu, mloc, off));

            float mnew = fmaxf(m_run[i], mloc);
            float corr = exp2f(m_run[i] - mnew);   // exp2f(-inf) = 0 on first tile
            m_run[i] = mnew;
            l_run[i] *= corr;

            float psum = 0.f;
            #pragma unroll
            for (int j = 0; j < 4; j++) {
                float p = exp2f(fmaf(s[j], C2F, -mnew));
                sp[(r0 + i) * PPAD + mc + 16 * j] = p;
                psum += p;
            }
            #pragma unroll
            for (int off = 1; off < 16; off <<= 1)
                psum += __shfl_xor_sync(0xffffffffu, psum, off);
            l_run[i] += psum;

            unsigned long long corr2;
            PACK2(corr2, corr, corr);
            #pragma unroll
            for (int d = 0; d < 4; d++) MUL2(o2[i][d], corr2);
        }
        // P rows r0..r0+3 are produced entirely by this warp's 16-lane group.
        __syncwarp();

        // ---- GEMM2 (packed col-pairs): o2[i][.] += p[r0+i][j] * kv[j][cols] ----
        #pragma unroll 1
        for (int jb4 = 0; jb4 < BN; jb4 += 4) {
            float4 P4[4];
            #pragma unroll
            for (int i = 0; i < 4; i++)       // broadcast (2 unique per warp)
                P4[i] = *(const float4*)&sp[(r0 + i) * PPAD + jb4];
            #pragma unroll
            for (int jj = 0; jj < 4; jj++) {
                int jr = jb4 + jj;
                // 16B chunks at byte stride 16 across lanes: 2-way (minimum)
                ulonglong2 vA = *(const ulonglong2*)&skv[jr * KVPAD + dcA];
                ulonglong2 vB = *(const ulonglong2*)&skv[jr * KVPAD + dcB];
                #pragma unroll
                for (int i = 0; i < 4; i++) {
                    const float* pf = (const float*)&P4[i];
                    float pv = pf[jj];
                    unsigned long long pp;
                    PACK2(pp, pv, pv);
                    FMA2(o2[i][0], pp, vA.x);
                    FMA2(o2[i][1], pp, vA.y);
                    FMA2(o2[i][2], pp, vB.x);
                    FMA2(o2[i][3], pp, vB.y);
                }
            }
        }
        __syncthreads();   // before next tile overwrites skv
    }

    // ---- epilogue: normalize and store ----
    #pragma unroll
    for (int i = 0; i < 4; i++) {
        float inv = 1.0f / l_run[i];
        float f[8];
        #pragma unroll
        for (int d = 0; d < 4; d++) {
            float lo, hi;
            UNPACK2(lo, hi, o2[i][d]);
            f[2 * d]     = lo * inv;
            f[2 * d + 1] = hi * inv;
        }
        float* dst = OUT + (size_t)(qbase + r0 + i) * DD;
        float4 wA = make_float4(f[0], f[1], f[2], f[3]);
        float4 wB = make_float4(f[4], f[5], f[6], f[7]);
        *(float4*)(dst + dcA) = wA;
        *(float4*)(dst + dcB) = wB;
    }
}

extern "C" void kernel_launch(void* const* d_in, const int* in_sizes, int n_in,
                              void* d_out, int out_size)
{
    const float* p1 = (const float*)d_in[0];
    const float* p2 = (const float*)d_in[1];
    float* out = (float*)d_out;

    const int smem_bytes = (BM * KVPAD + BN * KVPAD + BM * PPAD) * (int)sizeof(float);
    cudaFuncSetAttribute(attn_fwd_kernel,
                         cudaFuncAttributeMaxDynamicSharedMemorySize, smem_bytes);

    attn_fwd_kernel<<<N1v / BM, NTHREADS, smem_bytes>>>(p1, p2, out);
}

// round 6
// speedup vs baseline: 1.1337x; 1.1337x over previous
#include <cuda_runtime.h>
#include <math_constants.h>

// out = softmax(p1 @ p2^T * sqrt(N2)) @ p2 ; N1=N2=8192, D=128, fp32.
//
// Round 6: CUDA-core f32x2 kernel (tcgen05 PTX is rejected by the harness's
// compute_103 PTX target, so tensor cores are unavailable in this bench).
// Changes vs the 987us kernel:
//   * split-KV x2 -> grid 256, __launch_bounds__(256,2): 2 CTAs/SM,
//     16 warps/SM for latency hiding (was 8).
//   * GEMM1 inner loop restructured (single A register pair per row) to fit
//     the 128-reg budget that 2 CTAs/SM requires.
//   * partial (m,l,O/l) per half into __device__ scratch + tiny merge kernel.

#define N1v 8192
#define N2v 8192
#define DD  128
#define BM  64
#define BN  64
#define NKV_HALF 4096
#define KVPAD 132   // row stride (floats); lane-row bank stride 4*mc: 2-way min
#define PPAD  68
#define NTHREADS 256
#define C2F 130.57784f   // sqrt(8192) * log2(e)

// packed f32x2 ops (ptxas never auto-fuses these from C++)
#define FMA2(d, a, b) asm("fma.rn.f32x2 %0, %1, %2, %0;" : "+l"(d) : "l"(a), "l"(b))
#define MUL2(d, s)    asm("mul.rn.f32x2 %0, %0, %1;"     : "+l"(d) : "l"(s))
#define PACK2(d, x, y) asm("mov.b64 %0, {%1, %2};" : "=l"(d) : "f"(x), "f"(y))
#define UNPACK2(lo, hi, v) asm("mov.b64 {%0, %1}, %2;" : "=f"(lo), "=f"(hi) : "l"(v))

// ---- split-KV scratch (static device globals: no runtime allocation) ----
__device__ float g_opart[2][N1v][DD];
__device__ float g_m[2][N1v];
__device__ float g_l[2][N1v];

__global__ __launch_bounds__(NTHREADS, 2)
void attn_fwd_kernel(const float* __restrict__ P1,
                     const float* __restrict__ P2)
{
    extern __shared__ float smem[];
    float* sq  = smem;                      // [BM][KVPAD]
    float* skv = sq  + BM * KVPAD;          // [BN][KVPAD]
    float* sp  = skv + BN * KVPAD;          // [BM][PPAD]

    const int t   = threadIdx.x;
    const int mr  = t >> 4;                 // 0..15  row-group id
    const int mc  = t & 15;                 // 0..15  lane within row-group
    const int r0  = mr * 4;                 // this thread's 4 score/output rows
    const int dcA = 4 * mc;                 // GEMM2 output cols {4mc..4mc+3}
    const int dcB = 64 + 4 * mc;            //                  {64+4mc..}
    const int qt    = blockIdx.x >> 1;
    const int half  = blockIdx.x & 1;
    const int qbase = qt * BM;
    const int kv0   = half * NKV_HALF;

    // ---- load Q tile (BM x 128 floats = 2048 float4, 8 per thread) ----
    {
        const float4* src = (const float4*)(P1 + (size_t)qbase * DD);
        #pragma unroll
        for (int i = 0; i < 8; i++) {
            int idx = t + i * NTHREADS;       // 0..2047
            int row = idx >> 5;               // 32 float4 per row
            int c4  = idx & 31;
            float4 v = src[idx];
            *(float4*)&sq[row * KVPAD + c4 * 4] = v;
        }
    }

    // ---- running softmax state + packed O accumulators ----
    float m_run[4], l_run[4];
    unsigned long long o2[4][4];            // 4 rows x 4 col-pairs (8 cols)
    #pragma unroll
    for (int i = 0; i < 4; i++) {
        m_run[i] = -CUDART_INF_F;
        l_run[i] = 0.f;
        #pragma unroll
        for (int d = 0; d < 4; d++) o2[i][d] = 0ull;
    }

    __syncthreads();

    for (int it = 0; it < NKV_HALF / BN; it++) {
        const int jb = kv0 + it * BN;

        // ---- load KV tile ----
        {
            const float4* src = (const float4*)(P2 + (size_t)jb * DD);
            #pragma unroll
            for (int i = 0; i < 8; i++) {
                int idx = t + i * NTHREADS;
                int row = idx >> 5;
                int c4  = idx & 31;
                float4 v = src[idx];
                *(float4*)&skv[row * KVPAD + c4 * 4] = v;
            }
        }
        __syncthreads();

        // ---- GEMM1 (packed k-pairs): acc2[i][j] = q[r0+i] . kv[mc+16j] ----
        unsigned long long acc2[4][4];
        #pragma unroll
        for (int i = 0; i < 4; i++)
            #pragma unroll
            for (int j = 0; j < 4; j++) acc2[i][j] = 0ull;

        #pragma unroll 2
        for (int k = 0; k < DD; k += 4) {
            ulonglong2 B[4];
            #pragma unroll
            for (int j = 0; j < 4; j++)       // lane-varying rows: 2-way min conflicts
                B[j] = *(const ulonglong2*)&skv[(mc + 16 * j) * KVPAD + k];
            #pragma unroll
            for (int i = 0; i < 4; i++) {     // single A buffer per row (reg budget)
                ulonglong2 A = *(const ulonglong2*)&sq[(r0 + i) * KVPAD + k];
                #pragma unroll
                for (int j = 0; j < 4; j++) {
                    FMA2(acc2[i][j], A.x, B[j].x);
                    FMA2(acc2[i][j], A.y, B[j].y);
                }
            }
        }

        // ---- online softmax (per row, reduced across the 16-lane row group) ----
        #pragma unroll
        for (int i = 0; i < 4; i++) {
            float s[4];
            #pragma unroll
            for (int j = 0; j < 4; j++) {
                float lo, hi;
                UNPACK2(lo, hi, acc2[i][j]);
                s[j] = lo + hi;
            }
            float mloc = fmaxf(fmaxf(s[0], s[1]), fmaxf(s[2], s[3]));
            mloc *= C2F;   // logits in log2 domain
            #pragma unroll
            for (int off = 1; off < 16; off <<= 1)
                mloc = fmaxf(mloc, __shfl_xor_sync(0xffffffffu, mloc, off));

            float mnew = fmaxf(m_run[i], mloc);
            float corr = exp2f(m_run[i] - mnew);   // exp2f(-inf)=0 first tile
            m_run[i] = mnew;
            l_run[i] *= corr;

            float psum = 0.f;
            #pragma unroll
            for (int j = 0; j < 4; j++) {
                float p = exp2f(fmaf(s[j], C2F, -mnew));
                sp[(r0 + i) * PPAD + mc + 16 * j] = p;
                psum += p;
            }
            #pragma unroll
            for (int off = 1; off < 16; off <<= 1)
                psum += __shfl_xor_sync(0xffffffffu, psum, off);
            l_run[i] += psum;

            unsigned long long corr2;
            PACK2(corr2, corr, corr);
            #pragma unroll
            for (int d = 0; d < 4; d++) MUL2(o2[i][d], corr2);
        }
        // P rows r0..r0+3 produced entirely by this warp's 16-lane group.
        __syncwarp();

        // ---- GEMM2 (packed col-pairs): o2[i][.] += p[r0+i][j] * kv[j][cols] ----
        #pragma unroll 1
        for (int jb4 = 0; jb4 < BN; jb4 += 4) {
            float4 P4[4];
            #pragma unroll
            for (int i = 0; i < 4; i++)       // broadcast (2 unique addrs per warp)
                P4[i] = *(const float4*)&sp[(r0 + i) * PPAD + jb4];
            #pragma unroll
            for (int jj = 0; jj < 4; jj++) {
                int jr = jb4 + jj;
                // 16B chunks at 16B lane stride: 2-way (minimum)
                ulonglong2 vA = *(const ulonglong2*)&skv[jr * KVPAD + dcA];
                ulonglong2 vB = *(const ulonglong2*)&skv[jr * KVPAD + dcB];
                #pragma unroll
                for (int i = 0; i < 4; i++) {
                    float pv = ((const float*)&P4[i])[jj];
                    unsigned long long pp;
                    PACK2(pp, pv, pv);
                    FMA2(o2[i][0], pp, vA.x);
                    FMA2(o2[i][1], pp, vA.y);
                    FMA2(o2[i][2], pp, vB.x);
                    FMA2(o2[i][3], pp, vB.y);
                }
            }
        }
        __syncthreads();   // before next tile overwrites skv
    }

    // ---- epilogue: per-half normalized partial + (m,l) for the merge ----
    if (mc == 0) {
        #pragma unroll
        for (int i = 0; i < 4; i++) {
            g_m[half][qbase + r0 + i] = m_run[i];
            g_l[half][qbase + r0 + i] = l_run[i];
        }
    }
    #pragma unroll
    for (int i = 0; i < 4; i++) {
        float inv = 1.0f / l_run[i];
        float f[8];
        #pragma unroll
        for (int d = 0; d < 4; d++) {
            float lo, hi;
            UNPACK2(lo, hi, o2[i][d]);
            f[2 * d]     = lo * inv;
            f[2 * d + 1] = hi * inv;
        }
        float* dst = &g_opart[half][qbase + r0 + i][0];
        *(float4*)(dst + dcA) = make_float4(f[0], f[1], f[2], f[3]);
        *(float4*)(dst + dcB) = make_float4(f[4], f[5], f[6], f[7]);
    }
}

// combine the two KV halves:  out = (w0*o0 + w1*o1)/(w0+w1),  w = l * 2^(m-M)
__global__ void merge_kernel(float* __restrict__ out)
{
    int idx = blockIdx.x * blockDim.x + threadIdx.x;   // over 8192*128
    int row = idx >> 7;
    float m0 = g_m[0][row], m1 = g_m[1][row];
    float M  = fmaxf(m0, m1);
    float w0 = g_l[0][row] * exp2f(m0 - M);
    float w1 = g_l[1][row] * exp2f(m1 - M);
    int col = idx & (DD - 1);
    out[idx] = (w0 * g_opart[0][row][col] + w1 * g_opart[1][row][col]) / (w0 + w1);
}

extern "C" void kernel_launch(void* const* d_in, const int* in_sizes, int n_in,
                              void* d_out, int out_size)
{
    const float* p1 = (const float*)d_in[0];
    const float* p2 = (const float*)d_in[1];
    float* out = (float*)d_out;

    const int smem_bytes = (BM * KVPAD + BN * KVPAD + BM * PPAD) * (int)sizeof(float);
    cudaFuncSetAttribute(attn_fwd_kernel,
                         cudaFuncAttributeMaxDynamicSharedMemorySize, smem_bytes);

    attn_fwd_kernel<<<(N1v / BM) * 2, NTHREADS, smem_bytes>>>(p1, p2);
    merge_kernel<<<(N1v * DD) / 256, 256>>>(out);
}

// round 7
// speedup vs baseline: 1.1364x; 1.0024x over previous
#include <cuda_runtime.h>
#include <math_constants.h>

// out = softmax(p1 @ p2^T * sqrt(N2)) @ p2 ; N1=N2=8192, D=128, fp32.
//
// Round 6: CUDA-core f32x2 kernel (tcgen05 PTX is rejected by the harness's
// compute_103 PTX target, so tensor cores are unavailable in this bench).
// Changes vs the 987us kernel:
//   * split-KV x2 -> grid 256, __launch_bounds__(256,2): 2 CTAs/SM,
//     16 warps/SM for latency hiding (was 8).
//   * GEMM1 inner loop restructured (single A register pair per row) to fit
//     the 128-reg budget that 2 CTAs/SM requires.
//   * partial (m,l,O/l) per half into __device__ scratch + tiny merge kernel.

#define N1v 8192
#define N2v 8192
#define DD  128
#define BM  64
#define BN  64
#define NKV_HALF 4096
#define KVPAD 132   // row stride (floats); lane-row bank stride 4*mc: 2-way min
#define PPAD  68
#define NTHREADS 256
#define C2F 130.57784f   // sqrt(8192) * log2(e)

// packed f32x2 ops (ptxas never auto-fuses these from C++)
#define FMA2(d, a, b) asm("fma.rn.f32x2 %0, %1, %2, %0;" : "+l"(d) : "l"(a), "l"(b))
#define MUL2(d, s)    asm("mul.rn.f32x2 %0, %0, %1;"     : "+l"(d) : "l"(s))
#define PACK2(d, x, y) asm("mov.b64 %0, {%1, %2};" : "=l"(d) : "f"(x), "f"(y))
#define UNPACK2(lo, hi, v) asm("mov.b64 {%0, %1}, %2;" : "=f"(lo), "=f"(hi) : "l"(v))

// ---- split-KV scratch (static device globals: no runtime allocation) ----
__device__ float g_opart[2][N1v][DD];
__device__ float g_m[2][N1v];
__device__ float g_l[2][N1v];

__global__ __launch_bounds__(NTHREADS, 2)
void attn_fwd_kernel(const float* __restrict__ P1,
                     const float* __restrict__ P2)
{
    extern __shared__ float smem[];
    float* sq  = smem;                      // [BM][KVPAD]
    float* skv = sq  + BM * KVPAD;          // [BN][KVPAD]
    float* sp  = skv + BN * KVPAD;          // [BM][PPAD]

    const int t   = threadIdx.x;
    const int mr  = t >> 4;                 // 0..15  row-group id
    const int mc  = t & 15;                 // 0..15  lane within row-group
    const int r0  = mr * 4;                 // this thread's 4 score/output rows
    const int dcA = 4 * mc;                 // GEMM2 output cols {4mc..4mc+3}
    const int dcB = 64 + 4 * mc;            //                  {64+4mc..}
    const int qt    = blockIdx.x >> 1;
    const int half  = blockIdx.x & 1;
    const int qbase = qt * BM;
    const int kv0   = half * NKV_HALF;

    // ---- load Q tile (BM x 128 floats = 2048 float4, 8 per thread) ----
    {
        const float4* src = (const float4*)(P1 + (size_t)qbase * DD);
        #pragma unroll
        for (int i = 0; i < 8; i++) {
            int idx = t + i * NTHREADS;       // 0..2047
            int row = idx >> 5;               // 32 float4 per row
            int c4  = idx & 31;
            float4 v = src[idx];
            *(float4*)&sq[row * KVPAD + c4 * 4] = v;
        }
    }

    // ---- running softmax state + packed O accumulators ----
    float m_run[4], l_run[4];
    unsigned long long o2[4][4];            // 4 rows x 4 col-pairs (8 cols)
    #pragma unroll
    for (int i = 0; i < 4; i++) {
        m_run[i] = -CUDART_INF_F;
        l_run[i] = 0.f;
        #pragma unroll
        for (int d = 0; d < 4; d++) o2[i][d] = 0ull;
    }

    __syncthreads();

    for (int it = 0; it < NKV_HALF / BN; it++) {
        const int jb = kv0 + it * BN;

        // ---- load KV tile ----
        {
            const float4* src = (const float4*)(P2 + (size_t)jb * DD);
            #pragma unroll
            for (int i = 0; i < 8; i++) {
                int idx = t + i * NTHREADS;
                int row = idx >> 5;
                int c4  = idx & 31;
                float4 v = src[idx];
                *(float4*)&skv[row * KVPAD + c4 * 4] = v;
            }
        }
        __syncthreads();

        // ---- GEMM1 (packed k-pairs): acc2[i][j] = q[r0+i] . kv[mc+16j] ----
        unsigned long long acc2[4][4];
        #pragma unroll
        for (int i = 0; i < 4; i++)
            #pragma unroll
            for (int j = 0; j < 4; j++) acc2[i][j] = 0ull;

        #pragma unroll 2
        for (int k = 0; k < DD; k += 4) {
            ulonglong2 B[4];
            #pragma unroll
            for (int j = 0; j < 4; j++)       // lane-varying rows: 2-way min conflicts
                B[j] = *(const ulonglong2*)&skv[(mc + 16 * j) * KVPAD + k];
            #pragma unroll
            for (int i = 0; i < 4; i++) {     // single A buffer per row (reg budget)
                ulonglong2 A = *(const ulonglong2*)&sq[(r0 + i) * KVPAD + k];
                #pragma unroll
                for (int j = 0; j < 4; j++) {
                    FMA2(acc2[i][j], A.x, B[j].x);
                    FMA2(acc2[i][j], A.y, B[j].y);
                }
            }
        }

        // ---- online softmax (per row, reduced across the 16-lane row group) ----
        #pragma unroll
        for (int i = 0; i < 4; i++) {
            float s[4];
            #pragma unroll
            for (int j = 0; j < 4; j++) {
                float lo, hi;
                UNPACK2(lo, hi, acc2[i][j]);
                s[j] = lo + hi;
            }
            float mloc = fmaxf(fmaxf(s[0], s[1]), fmaxf(s[2], s[3]));
            mloc *= C2F;   // logits in log2 domain
            #pragma unroll
            for (int off = 1; off < 16; off <<= 1)
                mloc = fmaxf(mloc, __shfl_xor_sync(0xffffffffu, mloc, off));

            float mnew = fmaxf(m_run[i], mloc);
            float corr = exp2f(m_run[i] - mnew);   // exp2f(-inf)=0 first tile
            m_run[i] = mnew;
            l_run[i] *= corr;

            float psum = 0.f;
            #pragma unroll
            for (int j = 0; j < 4; j++) {
                float p = exp2f(fmaf(s[j], C2F, -mnew));
                sp[(r0 + i) * PPAD + mc + 16 * j] = p;
                psum += p;
            }
            #pragma unroll
            for (int off = 1; off < 16; off <<= 1)
                psum += __shfl_xor_sync(0xffffffffu, psum, off);
            l_run[i] += psum;

            unsigned long long corr2;
            PACK2(corr2, corr, corr);
            #pragma unroll
            for (int d = 0; d < 4; d++) MUL2(o2[i][d], corr2);
        }
        // P rows r0..r0+3 produced entirely by this warp's 16-lane group.
        __syncwarp();

        // ---- GEMM2 (packed col-pairs): o2[i][.] += p[r0+i][j] * kv[j][cols] ----
        #pragma unroll 1
        for (int jb4 = 0; jb4 < BN; jb4 += 4) {
            float4 P4[4];
            #pragma unroll
            for (int i = 0; i < 4; i++)       // broadcast (2 unique addrs per warp)
                P4[i] = *(const float4*)&sp[(r0 + i) * PPAD + jb4];
            #pragma unroll
            for (int jj = 0; jj < 4; jj++) {
                int jr = jb4 + jj;
                // 16B chunks at 16B lane stride: 2-way (minimum)
                ulonglong2 vA = *(const ulonglong2*)&skv[jr * KVPAD + dcA];
                ulonglong2 vB = *(const ulonglong2*)&skv[jr * KVPAD + dcB];
                #pragma unroll
                for (int i = 0; i < 4; i++) {
                    float pv = ((const float*)&P4[i])[jj];
                    unsigned long long pp;
                    PACK2(pp, pv, pv);
                    FMA2(o2[i][0], pp, vA.x);
                    FMA2(o2[i][1], pp, vA.y);
                    FMA2(o2[i][2], pp, vB.x);
                    FMA2(o2[i][3], pp, vB.y);
                }
            }
        }
        __syncthreads();   // before next tile overwrites skv
    }

    // ---- epilogue: per-half normalized partial + (m,l) for the merge ----
    if (mc == 0) {
        #pragma unroll
        for (int i = 0; i < 4; i++) {
            g_m[half][qbase + r0 + i] = m_run[i];
            g_l[half][qbase + r0 + i] = l_run[i];
        }
    }
    #pragma unroll
    for (int i = 0; i < 4; i++) {
        float inv = 1.0f / l_run[i];
        float f[8];
        #pragma unroll
        for (int d = 0; d < 4; d++) {
            float lo, hi;
            UNPACK2(lo, hi, o2[i][d]);
            f[2 * d]     = lo * inv;
            f[2 * d + 1] = hi * inv;
        }
        float* dst = &g_opart[half][qbase + r0 + i][0];
        *(float4*)(dst + dcA) = make_float4(f[0], f[1], f[2], f[3]);
        *(float4*)(dst + dcB) = make_float4(f[4], f[5], f[6], f[7]);
    }
}

// combine the two KV halves:  out = (w0*o0 + w1*o1)/(w0+w1),  w = l * 2^(m-M)
__global__ void merge_kernel(float* __restrict__ out)
{
    int idx = blockIdx.x * blockDim.x + threadIdx.x;   // over 8192*128
    int row = idx >> 7;
    float m0 = g_m[0][row], m1 = g_m[1][row];
    float M  = fmaxf(m0, m1);
    float w0 = g_l[0][row] * exp2f(m0 - M);
    float w1 = g_l[1][row] * exp2f(m1 - M);
    int col = idx & (DD - 1);
    out[idx] = (w0 * g_opart[0][row][col] + w1 * g_opart[1][row][col]) / (w0 + w1);
}

extern "C" void kernel_launch(void* const* d_in, const int* in_sizes, int n_in,
                              void* d_out, int out_size)
{
    const float* p1 = (const float*)d_in[0];
    const float* p2 = (const float*)d_in[1];
    float* out = (float*)d_out;

    const int smem_bytes = (BM * KVPAD + BN * KVPAD + BM * PPAD) * (int)sizeof(float);
    cudaFuncSetAttribute(attn_fwd_kernel,
                         cudaFuncAttributeMaxDynamicSharedMemorySize, smem_bytes);

    attn_fwd_kernel<<<(N1v / BM) * 2, NTHREADS, smem_bytes>>>(p1, p2);
    merge_kernel<<<(N1v * DD) / 256, 256>>>(out);
}